// round 4
// baseline (speedup 1.0000x reference)
#include <cuda_runtime.h>
#include <cuda_bf16.h>
#include <math.h>

// Problem dims
#define BB 128
#define LC 512
#define LE 512
#define HH 512
#define VV 128
#define GG 2048           // 4*H
#define KENC 640          // V + H
#define KDEC 1152         // V + H(vprev) + H(h)
#define TDEC (LE - 1)     // 511 decoder steps
#define NCTA 128          // persistent grid size (all co-resident)

// ---------------- device scratch (static; no allocations) ----------------
__device__ float g_hA[BB * HH];
__device__ float g_hB[BB * HH];
__device__ float g_c[BB * HH];
__device__ float g_zero[BB * HH];
__device__ float g_q[BB * HH];
__device__ float g_attn[BB * HH];
__device__ float g_V[2][BB * HH];                           // ping-pong raw Vnew
__device__ __nv_bfloat16 g_ehs[(size_t)BB * LC * HH];       // 67 MB (b, l, h) bf16
__device__ float g_tvseq[(size_t)TDEC * BB * HH];           // 134 MB tanh(Vnew)
__device__ float g_logits[(size_t)TDEC * BB * VV];          // 33.5 MB
__device__ float g_Wenc[GG * KENC];                         // permuted [Wih | Whh]
__device__ float g_Wdec[GG * KDEC];                         // permuted [Wih_e | Wih_V | Whh]
__device__ float g_benc[GG];
__device__ float g_bdec[GG];
__device__ float g_part[512];

// ---------------- grid barrier state (monotonic generation; replay-safe) ---
__device__ unsigned g_bucket[8 * 32];   // 128B-strided buckets
__device__ unsigned g_root;
__device__ unsigned g_gen;

__device__ __forceinline__ unsigned ld_acq(unsigned* p) {
    unsigned v;
    asm volatile("ld.acquire.gpu.u32 %0, [%1];" : "=r"(v) : "l"(p));
    return v;
}

// Tree grid barrier: 8 buckets x 16 arrivals -> root x 8 -> gen bump.
// Spinners poll gen with acquire loads (no atomic contention).
__device__ __forceinline__ void grid_sync() {
    __syncthreads();
    if (threadIdx.x == 0) {
        unsigned gen = ld_acq(&g_gen);          // read BEFORE arriving
        __threadfence();                        // release our CTA's writes
        if (atomicAdd(&g_bucket[(blockIdx.x & 7) * 32], 1u) == 15u) {
            if (atomicAdd(&g_root, 1u) == 7u) { // unique last arriver
#pragma unroll
                for (int i = 0; i < 8; i++) g_bucket[i * 32] = 0u;
                g_root = 0u;
                __threadfence();
                atomicAdd(&g_gen, 1u);
            }
        }
        while (ld_acq(&g_gen) == gen) __nanosleep(64);
    }
    __syncthreads();
}

// ---------------- shared-memory overlay ----------------
struct SMg { float As[32][132]; float Ws[32][18]; float Gs[16][129]; };  // gates GEMM
struct SMs { float As[32][66];  float Ws[32][9]; };                      // 64x8 GEMM
struct SMa { float qs[HH]; float accs[8][HH]; float wm[8]; float wsum[8]; }; // attention
union SM { SMg g; SMs s; SMa a; };

// Gate-row permutation: new row r = 4*j + gate  ->  old row = gate*512 + j
__device__ __forceinline__ int old_row(int r) { return (r & 3) * HH + (r >> 2); }

// ---------------- prep: permuted weights + zero state ----------------
__global__ void prep_kernel(const float* __restrict__ eWih, const float* __restrict__ eWhh,
                            const float* __restrict__ eBih, const float* __restrict__ eBhh,
                            const float* __restrict__ dWih, const float* __restrict__ dWhh,
                            const float* __restrict__ dBih, const float* __restrict__ dBhh) {
    int idx = blockIdx.x * blockDim.x + threadIdx.x;
    int stride = gridDim.x * blockDim.x;
    for (int i = idx; i < GG * KENC; i += stride) {
        int r = i / KENC, k = i - r * KENC;
        int o = old_row(r);
        g_Wenc[i] = (k < VV) ? eWih[o * VV + k] : eWhh[o * HH + (k - VV)];
    }
    for (int i = idx; i < GG * KDEC; i += stride) {
        int r = i / KDEC, k = i - r * KDEC;
        int o = old_row(r);
        g_Wdec[i] = (k < VV + HH) ? dWih[o * (VV + HH) + k] : dWhh[o * HH + (k - VV - HH)];
    }
    for (int i = idx; i < GG; i += stride) {
        int o = old_row(i);
        g_benc[i] = eBih[o] + eBhh[o];
        g_bdec[i] = dBih[o] + dBhh[o];
    }
    for (int i = idx; i < BB * HH; i += stride) {
        g_hA[i] = 0.f; g_c[i] = 0.f; g_zero[i] = 0.f;
    }
}

// ---------------- gates GEMM + LSTM update (one 16-wide N tile per CTA) ------
// gates[m,n] = sum_k A[m,k]*W[n,k]; A = [x_t | (vprev) | h_in]
__device__ __forceinline__ void gates_tile(SM* sm,
    const float* __restrict__ x, int xstride,
    const float* __restrict__ vprev, const float* __restrict__ h_in,
    const float* __restrict__ W, const float* __restrict__ bias,
    int K, int hoff, float* __restrict__ h_out, int t, bool enc)
{
    int tx = threadIdx.x, nt = blockIdx.x;
    int mg = tx & 31, ng = tx >> 5;         // thread tile: 4 contiguous m x 2 contiguous n
    const float* Wbase = W + (size_t)nt * 16 * K;

    float acc[4][2];
#pragma unroll
    for (int i = 0; i < 4; i++) { acc[i][0] = 0.f; acc[i][1] = 0.f; }

    int mA = tx >> 1, kA0 = (tx & 1) * 16;  // A loader: 16 consecutive k per thread
    for (int k0 = 0; k0 < K; k0 += 32) {
#pragma unroll
        for (int q2 = 0; q2 < 4; q2++) {
            int kg = k0 + kA0 + q2 * 4;
            float4 v;
            if (kg < VV)        v = *(const float4*)(x + (size_t)mA * xstride + kg);
            else if (kg < hoff) v = *(const float4*)(vprev + mA * HH + (kg - VV));
            else                v = *(const float4*)(h_in + mA * HH + (kg - hoff));
            int kr = kA0 + q2 * 4;
            sm->g.As[kr + 0][mA] = v.x; sm->g.As[kr + 1][mA] = v.y;
            sm->g.As[kr + 2][mA] = v.z; sm->g.As[kr + 3][mA] = v.w;
        }
        {
            int n = tx >> 4, kp = (tx & 15) * 2;
            float2 w = *(const float2*)(Wbase + (size_t)n * K + k0 + kp);
            sm->g.Ws[kp + 0][n] = w.x; sm->g.Ws[kp + 1][n] = w.y;
        }
        __syncthreads();
#pragma unroll
        for (int kk = 0; kk < 32; kk++) {
            float4 a = *(const float4*)&sm->g.As[kk][4 * mg];   // LDS.128
            float2 w = *(const float2*)&sm->g.Ws[kk][2 * ng];   // LDS.64 broadcast
            acc[0][0] += a.x * w.x; acc[0][1] += a.x * w.y;
            acc[1][0] += a.y * w.x; acc[1][1] += a.y * w.y;
            acc[2][0] += a.z * w.x; acc[2][1] += a.z * w.y;
            acc[3][0] += a.w * w.x; acc[3][1] += a.w * w.y;
        }
        __syncthreads();
    }
#pragma unroll
    for (int i = 0; i < 4; i++) {
        sm->g.Gs[2 * ng + 0][4 * mg + i] = acc[i][0];
        sm->g.Gs[2 * ng + 1][4 * mg + i] = acc[i][1];
    }
    __syncthreads();

    // LSTM update: 128 m x 4 gate-quads = 512 cells, 2 per thread
#pragma unroll
    for (int u = 0; u < 2; u++) {
        int cell = tx * 2 + u;
        int m = cell >> 2, jj = cell & 3;
        float gi = sm->g.Gs[4 * jj + 0][m] + bias[nt * 16 + 4 * jj + 0];
        float gf = sm->g.Gs[4 * jj + 1][m] + bias[nt * 16 + 4 * jj + 1];
        float gg = sm->g.Gs[4 * jj + 2][m] + bias[nt * 16 + 4 * jj + 2];
        float go = sm->g.Gs[4 * jj + 3][m] + bias[nt * 16 + 4 * jj + 3];
        int j = nt * 4 + jj;
        float cold = g_c[m * HH + j];
        float ig = 1.f / (1.f + expf(-gi));
        float fg = 1.f / (1.f + expf(-gf));
        float og = 1.f / (1.f + expf(-go));
        float cn = fg * cold + ig * tanhf(gg);
        float hn = og * tanhf(cn);
        g_c[m * HH + j] = cn;
        h_out[m * HH + j] = hn;
        if (enc) g_ehs[((size_t)m * LC + t) * HH + j] = __float2bfloat16(hn);
    }
}

// ---------------- 64x8 tile GEMM (q-proj / out-proj), 128 tiles ----------------
__device__ __forceinline__ void gemm_64x8(SM* sm,
    const float* __restrict__ A0, const float* __restrict__ A1, int K0, int K,
    const float* __restrict__ W, const float* __restrict__ bias,
    float* __restrict__ out, float* __restrict__ outRaw, float* __restrict__ outTanh)
{
    int tx = threadIdx.x, cta = blockIdx.x;
    int m0 = (cta & 1) * 64, n0 = (cta >> 1) * 8;
    int mg = tx & 31, ng = tx >> 5;         // 2 contiguous m x 1 n
    float acc0 = 0.f, acc1 = 0.f;

    int rA = tx >> 2, kA0 = (tx & 3) * 8;
    for (int k0 = 0; k0 < K; k0 += 32) {
#pragma unroll
        for (int q2 = 0; q2 < 2; q2++) {
            int kg = k0 + kA0 + q2 * 4;
            const float* src = (kg < K0) ? (A0 + (size_t)(m0 + rA) * HH + kg)
                                         : (A1 + (size_t)(m0 + rA) * HH + (kg - K0));
            float4 v = *(const float4*)src;
            int kr = kA0 + q2 * 4;
            sm->s.As[kr + 0][rA] = v.x; sm->s.As[kr + 1][rA] = v.y;
            sm->s.As[kr + 2][rA] = v.z; sm->s.As[kr + 3][rA] = v.w;
        }
        {
            int n = tx >> 5, kk = tx & 31;
            sm->s.Ws[kk][n] = W[(size_t)(n0 + n) * K + k0 + kk];
        }
        __syncthreads();
#pragma unroll
        for (int kk = 0; kk < 32; kk++) {
            float2 a = *(const float2*)&sm->s.As[kk][2 * mg];
            float w = sm->s.Ws[kk][ng];
            acc0 += a.x * w; acc1 += a.y * w;
        }
        __syncthreads();
    }
    int n = n0 + ng;
    float b = bias ? bias[n] : 0.f;
    int m = m0 + 2 * mg;
    float v0 = acc0 + b, v1 = acc1 + b;
    if (outTanh) {
        outRaw[(size_t)m * HH + n] = v0;
        outRaw[(size_t)(m + 1) * HH + n] = v1;
        outTanh[(size_t)m * HH + n] = tanhf(v0);
        outTanh[(size_t)(m + 1) * HH + n] = tanhf(v1);
    } else {
        out[(size_t)m * HH + n] = v0;
        out[(size_t)(m + 1) * HH + n] = v1;
    }
}

// ---------------- flash attention over bf16 enc_hs, CTA per batch row --------
__device__ __forceinline__ void attn_phase(SM* sm, const int* __restrict__ C_pad) {
    int b = blockIdx.x;
    int tx = threadIdx.x, lane = tx & 31, w = tx >> 5;

    for (int i = tx; i < HH; i += 256) sm->a.qs[i] = g_q[b * HH + i];
    __syncthreads();

    float mw = -INFINITY, sw = 0.f;
    float2 acc[8];
#pragma unroll
    for (int j = 0; j < 8; j++) acc[j] = make_float2(0.f, 0.f);

    const __nv_bfloat162* base = (const __nv_bfloat162*)(g_ehs + (size_t)b * LC * HH);
    const int* pad = C_pad + b * LC;

    for (int l = w; l < LC; l += 8) {
        if (pad[l]) continue;
        const __nv_bfloat162* row = base + (size_t)l * (HH / 2);
        float2 v[8];
        float s = 0.f;
#pragma unroll
        for (int j = 0; j < 8; j++) {
            v[j] = __bfloat1622float2(row[lane + 32 * j]);
            s += v[j].x * sm->a.qs[2 * (lane + 32 * j)]
               + v[j].y * sm->a.qs[2 * (lane + 32 * j) + 1];
        }
#pragma unroll
        for (int o = 16; o; o >>= 1) s += __shfl_xor_sync(0xffffffffu, s, o);
        float mn = fmaxf(mw, s);
        float corr = __expf(mw - mn);
        float p = __expf(s - mn);
        sw = sw * corr + p;
#pragma unroll
        for (int j = 0; j < 8; j++) {
            acc[j].x = acc[j].x * corr + p * v[j].x;
            acc[j].y = acc[j].y * corr + p * v[j].y;
        }
        mw = mn;
    }
    if (lane == 0) { sm->a.wm[w] = mw; sm->a.wsum[w] = sw; }
#pragma unroll
    for (int j = 0; j < 8; j++) {
        sm->a.accs[w][2 * (lane + 32 * j)]     = acc[j].x;
        sm->a.accs[w][2 * (lane + 32 * j) + 1] = acc[j].y;
    }
    __syncthreads();

    float M = -INFINITY;
#pragma unroll
    for (int i = 0; i < 8; i++) M = fmaxf(M, sm->a.wm[i]);
    float sc[8];
    float S = 0.f;
#pragma unroll
    for (int i = 0; i < 8; i++) { sc[i] = __expf(sm->a.wm[i] - M); S += sm->a.wsum[i] * sc[i]; }
    float invS = 1.f / S;
    for (int h = tx; h < HH; h += 256) {
        float a = 0.f;
#pragma unroll
        for (int i = 0; i < 8; i++) a += sm->a.accs[i][h] * sc[i];
        g_attn[b * HH + h] = a * invS;
    }
}

// ---------------- persistent encoder: 512 steps, 1 barrier/step ----------------
__global__ __launch_bounds__(256) void encoder_kernel(const float* __restrict__ C) {
    __shared__ SM sm;
    for (int t = 0; t < LC; t++) {
        const float* h_in = (t & 1) ? g_hB : g_hA;
        float* h_out = (t & 1) ? g_hA : g_hB;
        gates_tile(&sm, C + (size_t)t * VV, LC * VV, g_zero, h_in,
                   g_Wenc, g_benc, KENC, VV, h_out, t, true);
        grid_sync();
    }
}

// ---------------- persistent decoder: 511 steps x 4 phases ----------------
__global__ __launch_bounds__(256) void decoder_kernel(
    const float* __restrict__ E_emb, const int* __restrict__ C_pad,
    const float* __restrict__ attW, const float* __restrict__ outW,
    const float* __restrict__ outb)
{
    __shared__ SM sm;
    for (int t = 0; t < TDEC; t++) {
        const float* h_in = (t & 1) ? g_hB : g_hA;
        float* h_out = (t & 1) ? g_hA : g_hB;
        const float* vprev = (t == 0) ? g_zero : g_V[(t + 1) & 1];
        gates_tile(&sm, E_emb + (size_t)t * VV, LE * VV, vprev, h_in,
                   g_Wdec, g_bdec, KDEC, VV + HH, h_out, t, false);
        grid_sync();
        gemm_64x8(&sm, h_out, nullptr, HH, HH, attW, nullptr, g_q, nullptr, nullptr);
        grid_sync();
        attn_phase(&sm, C_pad);
        grid_sync();
        gemm_64x8(&sm, h_out, g_attn, HH, 2 * HH, outW, outb,
                  nullptr, g_V[t & 1], g_tvseq + (size_t)t * BB * HH);
        grid_sync();
    }
}

// ---------------- vocab projection tail (parallel) ----------------
__global__ __launch_bounds__(256) void vocab_kernel(const float* __restrict__ vocW,
                                                    const float* __restrict__ vocb) {
    __shared__ float As[32][65];
    __shared__ float Ws[32][17];
    int tx = threadIdx.x, lane = tx & 31, warp = tx >> 5;
    size_t m0 = (size_t)blockIdx.y * 64;
    int n0 = blockIdx.x * 16;
    const float* Wbase = vocW + (size_t)n0 * HH;

    float acc[2][2];
    acc[0][0] = acc[0][1] = acc[1][0] = acc[1][1] = 0.f;

    int mA = tx >> 2, kA0 = (tx & 3) * 8;
    for (int k0 = 0; k0 < HH; k0 += 32) {
#pragma unroll
        for (int kk = 0; kk < 8; kk++)
            As[kA0 + kk][mA] = g_tvseq[(m0 + mA) * HH + k0 + kA0 + kk];
#pragma unroll
        for (int i = 0; i < 2; i++) {
            int idx = tx + i * 256;
            int n = idx >> 5, kk = idx & 31;
            Ws[kk][n] = Wbase[(size_t)n * HH + k0 + kk];
        }
        __syncthreads();
#pragma unroll
        for (int kk = 0; kk < 32; kk++) {
            float a0 = As[kk][lane], a1 = As[kk][lane + 32];
            float w0 = Ws[kk][2 * warp], w1 = Ws[kk][2 * warp + 1];
            acc[0][0] += a0 * w0; acc[0][1] += a0 * w1;
            acc[1][0] += a1 * w0; acc[1][1] += a1 * w1;
        }
        __syncthreads();
    }
#pragma unroll
    for (int i = 0; i < 2; i++) {
        size_t gm = m0 + lane + 32 * i;
#pragma unroll
        for (int j = 0; j < 2; j++) {
            int gn = n0 + 2 * warp + j;
            g_logits[gm * VV + gn] = acc[i][j] + vocb[gn];
        }
    }
}

// ---------------- cross entropy (deterministic 2-stage reduce) ----------------
__global__ void ce_rows_kernel(const int* __restrict__ Etok) {
    int gw = (blockIdx.x * blockDim.x + threadIdx.x) >> 5;
    int lane = threadIdx.x & 31;
    int nw = (gridDim.x * blockDim.x) >> 5;
    float nll = 0.f, cnt = 0.f;
    for (int r = gw; r < TDEC * BB; r += nw) {
        int tt = r >> 7, b = r & 127;
        int tgt = Etok[b * LE + tt + 1];
        if (tgt == 0) continue;
        const float* row = g_logits + (size_t)r * VV;
        float v0 = row[lane], v1 = row[lane + 32], v2 = row[lane + 64], v3 = row[lane + 96];
        float mx = fmaxf(fmaxf(v0, v1), fmaxf(v2, v3));
#pragma unroll
        for (int o = 16; o; o >>= 1) mx = fmaxf(mx, __shfl_xor_sync(0xffffffffu, mx, o));
        float se = __expf(v0 - mx) + __expf(v1 - mx) + __expf(v2 - mx) + __expf(v3 - mx);
#pragma unroll
        for (int o = 16; o; o >>= 1) se += __shfl_xor_sync(0xffffffffu, se, o);
        if (lane == 0) { nll += logf(se) + mx - row[tgt]; cnt += 1.f; }
    }
    __shared__ float sn[8], scn[8];
    int w = threadIdx.x >> 5;
    if (lane == 0) { sn[w] = nll; scn[w] = cnt; }
    __syncthreads();
    if (threadIdx.x == 0) {
        float a = 0.f, c2 = 0.f;
        for (int i = 0; i < 8; i++) { a += sn[i]; c2 += scn[i]; }
        g_part[blockIdx.x * 2] = a;
        g_part[blockIdx.x * 2 + 1] = c2;
    }
}

__global__ void ce_final_kernel(float* __restrict__ out) {
    if (threadIdx.x == 0) {
        float n = 0.f, c2 = 0.f;
        for (int i = 0; i < 256; i++) { n += g_part[2 * i]; c2 += g_part[2 * i + 1]; }
        out[0] = n / fmaxf(c2, 1.f);
    }
}

// ---------------- host orchestration: 6 graph nodes ----------------
extern "C" void kernel_launch(void* const* d_in, const int* in_sizes, int n_in,
                              void* d_out, int out_size) {
    const float* C      = (const float*)d_in[0];
    const int*   C_pad  = (const int*)  d_in[1];
    const int*   E      = (const int*)  d_in[2];
    const float* E_emb  = (const float*)d_in[3];
    const float* eWih   = (const float*)d_in[4];
    const float* eWhh   = (const float*)d_in[5];
    const float* eBih   = (const float*)d_in[6];
    const float* eBhh   = (const float*)d_in[7];
    const float* dWih   = (const float*)d_in[8];
    const float* dWhh   = (const float*)d_in[9];
    const float* dBih   = (const float*)d_in[10];
    const float* dBhh   = (const float*)d_in[11];
    const float* attW   = (const float*)d_in[12];
    const float* outW   = (const float*)d_in[13];
    const float* outb   = (const float*)d_in[14];
    const float* vocW   = (const float*)d_in[15];
    const float* vocb   = (const float*)d_in[16];

    prep_kernel<<<512, 256>>>(eWih, eWhh, eBih, eBhh, dWih, dWhh, dBih, dBhh);
    encoder_kernel<<<NCTA, 256>>>(C);
    decoder_kernel<<<NCTA, 256>>>(E_emb, C_pad, attW, outW, outb);
    vocab_kernel<<<dim3(VV / 16, (TDEC * BB) / 64), 256>>>(vocW, vocb);
    ce_rows_kernel<<<256, 256>>>(E);
    ce_final_kernel<<<1, 32>>>((float*)d_out);
}

// round 7
// speedup vs baseline: 1.0006x; 1.0006x over previous
#include <cuda_runtime.h>
#include <cuda_bf16.h>
#include <math.h>

// Problem dims
#define BB 128
#define LC 512
#define LE 512
#define HH 512
#define VV 128
#define GG 2048           // 4*H
#define KENC 640          // V + H
#define KDEC 1152         // V + H(vprev) + H(h)
#define TDEC (LE - 1)     // 511 decoder steps
#define NCTA 128          // persistent grid size (all co-resident)

// ---------------- device scratch (static; no allocations) ----------------
__device__ float g_hA[BB * HH];
__device__ float g_hB[BB * HH];
__device__ float g_c[BB * HH];
__device__ float g_zero[BB * HH];
__device__ float g_q[BB * HH];
__device__ float g_attn[BB * HH];
__device__ float g_V[2][BB * HH];                           // ping-pong raw Vnew
__device__ __nv_bfloat16 g_ehs[(size_t)BB * LC * HH];       // 67 MB (b, l, h) bf16
__device__ float g_tvseq[(size_t)TDEC * BB * HH];           // 134 MB tanh(Vnew)
__device__ float g_logits[(size_t)TDEC * BB * VV];          // 33.5 MB
__device__ float g_Wenc[GG * KENC];                         // permuted [Wih | Whh]
__device__ float g_Wdec[GG * KDEC];                         // permuted [Wih_e | Wih_V | Whh]
__device__ float g_benc[GG];
__device__ float g_bdec[GG];
__device__ float g_part[512];

// ---------------- grid barrier state (monotonic generation; replay-safe) ---
__device__ unsigned g_bucket[8 * 32];   // 128B-strided buckets
__device__ unsigned g_root;
__device__ unsigned g_gen;

__device__ __forceinline__ unsigned ld_acq(unsigned* p) {
    unsigned v;
    asm volatile("ld.acquire.gpu.u32 %0, [%1];" : "=r"(v) : "l"(p));
    return v;
}

__device__ __forceinline__ void grid_sync() {
    __syncthreads();
    if (threadIdx.x == 0) {
        unsigned gen = ld_acq(&g_gen);          // read BEFORE arriving
        __threadfence();                        // release our CTA's writes
        if (atomicAdd(&g_bucket[(blockIdx.x & 7) * 32], 1u) == 15u) {
            if (atomicAdd(&g_root, 1u) == 7u) { // unique last arriver
#pragma unroll
                for (int i = 0; i < 8; i++) g_bucket[i * 32] = 0u;
                g_root = 0u;
                __threadfence();
                atomicAdd(&g_gen, 1u);
            }
        }
        while (ld_acq(&g_gen) == gen) __nanosleep(32);
    }
    __syncthreads();
}

// ---------------- L2-only loads (cross-CTA data between grid barriers) -----
__device__ __forceinline__ float4 ldcg4(const float* p) {
    float4 v;
    asm volatile("ld.global.cg.v4.f32 {%0,%1,%2,%3}, [%4];"
                 : "=f"(v.x), "=f"(v.y), "=f"(v.z), "=f"(v.w) : "l"(p));
    return v;
}
__device__ __forceinline__ unsigned ldcg_u32(const unsigned* p) {
    unsigned v;
    asm volatile("ld.global.cg.u32 %0, [%1];" : "=r"(v) : "l"(p));
    return v;
}
__device__ __forceinline__ float ldcg_f32(const float* p) {
    float v;
    asm volatile("ld.global.cg.f32 %0, [%1];" : "=f"(v) : "l"(p));
    return v;
}

// ---------------- shared-memory layouts ----------------
struct GatesBufs { float As[2][32][132]; float Gs[16][129]; };
struct AttnBufs  { float qs[HH]; float accs[8][HH]; float wm[8]; float wsum[8]; };
struct SmallBufs { float As[2][32][68]; };
struct DecSmem {
    float Wg[KDEC][16];       // gates W slice, [k][n]
    float Wq[HH][8];          // attW slice  [k][n]
    float Wv[2 * HH][8];      // outW slice  [k][n]
    union { GatesBufs g; AttnBufs a; SmallBufs s; } u;
};
struct EncSmem {
    float Wg[KENC][16];
    union { GatesBufs g; } u;
};

// Gate-row permutation: new row r = 4*j + gate  ->  old row = gate*512 + j
__device__ __forceinline__ int old_row(int r) { return (r & 3) * HH + (r >> 2); }

// ---------------- prep: permuted weights + zero state ----------------
__global__ void prep_kernel(const float* __restrict__ eWih, const float* __restrict__ eWhh,
                            const float* __restrict__ eBih, const float* __restrict__ eBhh,
                            const float* __restrict__ dWih, const float* __restrict__ dWhh,
                            const float* __restrict__ dBih, const float* __restrict__ dBhh) {
    int idx = blockIdx.x * blockDim.x + threadIdx.x;
    int stride = gridDim.x * blockDim.x;
    for (int i = idx; i < GG * KENC; i += stride) {
        int r = i / KENC, k = i - r * KENC;
        int o = old_row(r);
        g_Wenc[i] = (k < VV) ? eWih[o * VV + k] : eWhh[o * HH + (k - VV)];
    }
    for (int i = idx; i < GG * KDEC; i += stride) {
        int r = i / KDEC, k = i - r * KDEC;
        int o = old_row(r);
        g_Wdec[i] = (k < VV + HH) ? dWih[o * (VV + HH) + k] : dWhh[o * HH + (k - VV - HH)];
    }
    for (int i = idx; i < GG; i += stride) {
        int o = old_row(i);
        g_benc[i] = eBih[o] + eBhh[o];
        g_bdec[i] = dBih[o] + dBhh[o];
    }
    for (int i = idx; i < BB * HH; i += stride) {
        g_hA[i] = 0.f; g_c[i] = 0.f; g_zero[i] = 0.f;
    }
}

// ---------------- gates A-chunk loader (chunk c -> As[buf]) -----------------
__device__ __forceinline__ void gates_loadA(GatesBufs* gb, int buf, int c,
    const float* __restrict__ x, int xstride,
    const float* __restrict__ vprev, const float* __restrict__ h_in, int hoff)
{
    int tx = threadIdx.x;
    int mA = tx >> 1, kA0 = (tx & 1) * 16;
    int k0 = c * 32;
#pragma unroll
    for (int q2 = 0; q2 < 4; q2++) {
        int kg = k0 + kA0 + q2 * 4;
        float4 v;
        if (kg < VV)        v = ldcg4(x + (size_t)mA * xstride + kg);
        else if (kg < hoff) v = ldcg4(vprev + mA * HH + (kg - VV));
        else                v = ldcg4(h_in + mA * HH + (kg - hoff));
        int kr = kA0 + q2 * 4;
        gb->As[buf][kr + 0][mA] = v.x; gb->As[buf][kr + 1][mA] = v.y;
        gb->As[buf][kr + 2][mA] = v.z; gb->As[buf][kr + 3][mA] = v.w;
    }
}

// ---------------- gates GEMM + LSTM update (W resident in smem) -------------
__device__ __forceinline__ void gates_tile(const float (*Wg)[16], GatesBufs* gb,
    const float* __restrict__ x, int xstride,
    const float* __restrict__ vprev, const float* __restrict__ h_in,
    const float* __restrict__ bias,
    int K, int hoff, float* __restrict__ h_out, int t, bool enc)
{
    int tx = threadIdx.x, nt = blockIdx.x;
    int mg = tx & 31, ng = tx >> 5;         // thread tile: 4 contiguous m x 2 contiguous n

    float acc[4][2];
#pragma unroll
    for (int i = 0; i < 4; i++) { acc[i][0] = 0.f; acc[i][1] = 0.f; }

    int nchunks = K / 32;
    gates_loadA(gb, 0, 0, x, xstride, vprev, h_in, hoff);
    __syncthreads();
    for (int c = 0; c < nchunks; c++) {
        int buf = c & 1;
        if (c + 1 < nchunks)
            gates_loadA(gb, buf ^ 1, c + 1, x, xstride, vprev, h_in, hoff);
        int k0 = c * 32;
#pragma unroll
        for (int kk = 0; kk < 32; kk++) {
            float4 a = *(const float4*)&gb->As[buf][kk][4 * mg];   // LDS.128
            float2 w = *(const float2*)&Wg[k0 + kk][2 * ng];       // LDS.64 broadcast
            acc[0][0] += a.x * w.x; acc[0][1] += a.x * w.y;
            acc[1][0] += a.y * w.x; acc[1][1] += a.y * w.y;
            acc[2][0] += a.z * w.x; acc[2][1] += a.z * w.y;
            acc[3][0] += a.w * w.x; acc[3][1] += a.w * w.y;
        }
        __syncthreads();
    }
#pragma unroll
    for (int i = 0; i < 4; i++) {
        gb->Gs[2 * ng + 0][4 * mg + i] = acc[i][0];
        gb->Gs[2 * ng + 1][4 * mg + i] = acc[i][1];
    }
    __syncthreads();

    // LSTM update: 128 m x 4 gate-quads = 512 cells, 2 per thread
#pragma unroll
    for (int u = 0; u < 2; u++) {
        int cell = tx * 2 + u;
        int m = cell >> 2, jj = cell & 3;
        float gi = gb->Gs[4 * jj + 0][m] + bias[nt * 16 + 4 * jj + 0];
        float gf = gb->Gs[4 * jj + 1][m] + bias[nt * 16 + 4 * jj + 1];
        float gg = gb->Gs[4 * jj + 2][m] + bias[nt * 16 + 4 * jj + 2];
        float go = gb->Gs[4 * jj + 3][m] + bias[nt * 16 + 4 * jj + 3];
        int j = nt * 4 + jj;
        float cold = g_c[m * HH + j];
        float ig = 1.f / (1.f + expf(-gi));
        float fg = 1.f / (1.f + expf(-gf));
        float og = 1.f / (1.f + expf(-go));
        float cn = fg * cold + ig * tanhf(gg);
        float hn = og * tanhf(cn);
        g_c[m * HH + j] = cn;
        h_out[m * HH + j] = hn;
        if (enc) g_ehs[((size_t)m * LC + t) * HH + j] = __float2bfloat16(hn);
    }
    __syncthreads();    // protect Gs before union reuse
}

// ---------------- small GEMM 64x8 (q / out proj), W resident ----------------
__device__ __forceinline__ void small_loadA(SmallBufs* sb, int buf, int c,
    const float* __restrict__ A0, const float* __restrict__ A1, int K0, int m0)
{
    int tx = threadIdx.x;
    int rA = tx >> 2, kA0 = (tx & 3) * 8;
#pragma unroll
    for (int q2 = 0; q2 < 2; q2++) {
        int kg = c * 32 + kA0 + q2 * 4;
        const float* src = (kg < K0) ? (A0 + (size_t)(m0 + rA) * HH + kg)
                                     : (A1 + (size_t)(m0 + rA) * HH + (kg - K0));
        float4 v = ldcg4(src);
        int kr = kA0 + q2 * 4;
        sb->As[buf][kr + 0][rA] = v.x; sb->As[buf][kr + 1][rA] = v.y;
        sb->As[buf][kr + 2][rA] = v.z; sb->As[buf][kr + 3][rA] = v.w;
    }
}

__device__ __forceinline__ void gemm_small(const float (*Wsm)[8], SmallBufs* sb,
    const float* __restrict__ A0, const float* __restrict__ A1, int K0, int K,
    const float* __restrict__ bias,
    float* __restrict__ out, float* __restrict__ outRaw, float* __restrict__ outTanh)
{
    int tx = threadIdx.x, cta = blockIdx.x;
    int m0 = (cta & 1) * 64;
    int n0 = (cta >> 1) * 8;
    int mg = tx & 31, ng = tx >> 5;         // 2 contiguous m x 1 n
    float acc0 = 0.f, acc1 = 0.f;

    int nchunks = K / 32;
    small_loadA(sb, 0, 0, A0, A1, K0, m0);
    __syncthreads();
    for (int c = 0; c < nchunks; c++) {
        int buf = c & 1;
        if (c + 1 < nchunks) small_loadA(sb, buf ^ 1, c + 1, A0, A1, K0, m0);
        int k0 = c * 32;
#pragma unroll
        for (int kk = 0; kk < 32; kk++) {
            float2 a = *(const float2*)&sb->As[buf][kk][2 * mg];
            float w = Wsm[k0 + kk][ng];
            acc0 += a.x * w; acc1 += a.y * w;
        }
        __syncthreads();
    }
    int n = n0 + ng;
    float b = bias ? bias[n] : 0.f;
    int m = m0 + 2 * mg;
    float v0 = acc0 + b, v1 = acc1 + b;
    if (outTanh) {
        outRaw[(size_t)m * HH + n] = v0;
        outRaw[(size_t)(m + 1) * HH + n] = v1;
        outTanh[(size_t)m * HH + n] = tanhf(v0);
        outTanh[(size_t)(m + 1) * HH + n] = tanhf(v1);
    } else {
        out[(size_t)m * HH + n] = v0;
        out[(size_t)(m + 1) * HH + n] = v1;
    }
}

// ---------------- flash attention over bf16 enc_hs, CTA per batch row --------
__device__ __forceinline__ void attn_phase(AttnBufs* sa, const int* __restrict__ C_pad) {
    int b = blockIdx.x;
    int tx = threadIdx.x, lane = tx & 31, w = tx >> 5;

    for (int i = tx; i < HH; i += 256) sa->qs[i] = ldcg_f32(&g_q[b * HH + i]);
    __syncthreads();

    float mw = -INFINITY, sw = 0.f;
    float2 acc[8];
#pragma unroll
    for (int j = 0; j < 8; j++) acc[j] = make_float2(0.f, 0.f);

    const float* base4 = (const float*)(g_ehs + (size_t)b * LC * HH);
    const int* pad = C_pad + b * LC;

    for (int l = w; l < LC; l += 8) {
        if (pad[l]) continue;
        const float* row = base4 + (size_t)l * (HH / 2);   // bf16 pairs viewed as floats
        float2 v[8];
        float s = 0.f;
#pragma unroll
        for (int j = 0; j < 8; j++) {
            unsigned pk = ldcg_u32((const unsigned*)(row + lane + 32 * j));
            v[j] = __bfloat1622float2(*(__nv_bfloat162*)&pk);
            s += v[j].x * sa->qs[2 * (lane + 32 * j)]
               + v[j].y * sa->qs[2 * (lane + 32 * j) + 1];
        }
#pragma unroll
        for (int o = 16; o; o >>= 1) s += __shfl_xor_sync(0xffffffffu, s, o);
        float mn = fmaxf(mw, s);
        float corr = __expf(mw - mn);
        float p = __expf(s - mn);
        sw = sw * corr + p;
#pragma unroll
        for (int j = 0; j < 8; j++) {
            acc[j].x = acc[j].x * corr + p * v[j].x;
            acc[j].y = acc[j].y * corr + p * v[j].y;
        }
        mw = mn;
    }
    if (lane == 0) { sa->wm[w] = mw; sa->wsum[w] = sw; }
#pragma unroll
    for (int j = 0; j < 8; j++) {
        sa->accs[w][2 * (lane + 32 * j)]     = acc[j].x;
        sa->accs[w][2 * (lane + 32 * j) + 1] = acc[j].y;
    }
    __syncthreads();

    float M = -INFINITY;
#pragma unroll
    for (int i = 0; i < 8; i++) M = fmaxf(M, sa->wm[i]);
    float sc[8];
    float S = 0.f;
#pragma unroll
    for (int i = 0; i < 8; i++) { sc[i] = __expf(sa->wm[i] - M); S += sa->wsum[i] * sc[i]; }
    float invS = 1.f / S;
    for (int h = tx; h < HH; h += 256) {
        float a = 0.f;
#pragma unroll
        for (int i = 0; i < 8; i++) a += sa->accs[i][h] * sc[i];
        g_attn[b * HH + h] = a * invS;
    }
    __syncthreads();    // protect accs before union reuse
}

// ---------------- persistent encoder: 512 steps, 1 barrier/step ----------------
__global__ __launch_bounds__(256, 1) void encoder_kernel(const float* __restrict__ C) {
    extern __shared__ unsigned char s_raw[];
    EncSmem* sm = (EncSmem*)s_raw;
    int tx = threadIdx.x, nt = blockIdx.x;
    // preload W slice once: [k][n], coalesced GMEM reads
    for (int n = 0; n < 16; n++)
        for (int k = tx; k < KENC; k += 256)
            sm->Wg[k][n] = g_Wenc[(size_t)(nt * 16 + n) * KENC + k];
    __syncthreads();

    for (int t = 0; t < LC; t++) {
        const float* h_in = (t & 1) ? g_hB : g_hA;
        float* h_out = (t & 1) ? g_hA : g_hB;
        gates_tile(sm->Wg, &sm->u.g, C + (size_t)t * VV, LC * VV, g_zero, h_in,
                   g_benc, KENC, VV, h_out, t, true);
        grid_sync();
    }
}

// ---------------- persistent decoder: 511 steps x 4 phases ----------------
__global__ __launch_bounds__(256, 1) void decoder_kernel(
    const float* __restrict__ E_emb, const int* __restrict__ C_pad,
    const float* __restrict__ attW, const float* __restrict__ outW,
    const float* __restrict__ outb)
{
    extern __shared__ unsigned char s_raw[];
    DecSmem* sm = (DecSmem*)s_raw;
    int tx = threadIdx.x, nt = blockIdx.x;
    int n0s = (nt >> 1) * 8;       // small-gemm n-block
    // preload all weight slices once
    for (int n = 0; n < 16; n++)
        for (int k = tx; k < KDEC; k += 256)
            sm->Wg[k][n] = g_Wdec[(size_t)(nt * 16 + n) * KDEC + k];
    for (int n = 0; n < 8; n++) {
        for (int k = tx; k < HH; k += 256)
            sm->Wq[k][n] = attW[(size_t)(n0s + n) * HH + k];
        for (int k = tx; k < 2 * HH; k += 256)
            sm->Wv[k][n] = outW[(size_t)(n0s + n) * (2 * HH) + k];
    }
    __syncthreads();

    for (int t = 0; t < TDEC; t++) {
        const float* h_in = (t & 1) ? g_hB : g_hA;
        float* h_out = (t & 1) ? g_hA : g_hB;
        const float* vprev = (t == 0) ? g_zero : g_V[(t + 1) & 1];
        gates_tile(sm->Wg, &sm->u.g, E_emb + (size_t)t * VV, LE * VV, vprev, h_in,
                   g_bdec, KDEC, VV + HH, h_out, t, false);
        grid_sync();
        gemm_small(sm->Wq, &sm->u.s, h_out, nullptr, HH, HH, nullptr,
                   g_q, nullptr, nullptr);
        grid_sync();
        attn_phase(&sm->u.a, C_pad);
        grid_sync();
        gemm_small(sm->Wv, &sm->u.s, h_out, g_attn, HH, 2 * HH, outb,
                   nullptr, g_V[t & 1], g_tvseq + (size_t)t * BB * HH);
        grid_sync();
    }
}

// ---------------- vocab projection tail: 128x32 tile, 4x4/thread ------------
__global__ __launch_bounds__(256) void vocab_kernel(const float* __restrict__ vocW,
                                                    const float* __restrict__ vocb) {
    __shared__ float As[32][132];
    __shared__ float Ws[32][36];
    int tx = threadIdx.x;
    int mg = tx & 31, ng = tx >> 5;
    size_t m0 = (size_t)blockIdx.y * 128;
    int n0 = blockIdx.x * 32;

    float acc[4][4];
#pragma unroll
    for (int i = 0; i < 4; i++)
#pragma unroll
        for (int j = 0; j < 4; j++) acc[i][j] = 0.f;

    int mA = tx >> 1, kA0 = (tx & 1) * 16;
    int nW = tx >> 3, kW0 = (tx & 7) * 4;
    for (int k0 = 0; k0 < HH; k0 += 32) {
#pragma unroll
        for (int q2 = 0; q2 < 4; q2++) {
            float4 v = *(const float4*)&g_tvseq[(m0 + mA) * HH + k0 + kA0 + q2 * 4];
            int kr = kA0 + q2 * 4;
            As[kr + 0][mA] = v.x; As[kr + 1][mA] = v.y;
            As[kr + 2][mA] = v.z; As[kr + 3][mA] = v.w;
        }
        {
            float4 w = *(const float4*)&vocW[(size_t)(n0 + nW) * HH + k0 + kW0];
            Ws[kW0 + 0][nW] = w.x; Ws[kW0 + 1][nW] = w.y;
            Ws[kW0 + 2][nW] = w.z; Ws[kW0 + 3][nW] = w.w;
        }
        __syncthreads();
#pragma unroll
        for (int kk = 0; kk < 32; kk++) {
            float4 a = *(const float4*)&As[kk][4 * mg];
            float4 w = *(const float4*)&Ws[kk][4 * ng];
            acc[0][0] += a.x * w.x; acc[0][1] += a.x * w.y; acc[0][2] += a.x * w.z; acc[0][3] += a.x * w.w;
            acc[1][0] += a.y * w.x; acc[1][1] += a.y * w.y; acc[1][2] += a.y * w.z; acc[1][3] += a.y * w.w;
            acc[2][0] += a.z * w.x; acc[2][1] += a.z * w.y; acc[2][2] += a.z * w.z; acc[2][3] += a.z * w.w;
            acc[3][0] += a.w * w.x; acc[3][1] += a.w * w.y; acc[3][2] += a.w * w.z; acc[3][3] += a.w * w.w;
        }
        __syncthreads();
    }
#pragma unroll
    for (int i = 0; i < 4; i++) {
        size_t gm = m0 + 4 * mg + i;
#pragma unroll
        for (int j = 0; j < 4; j++) {
            int gn = n0 + 4 * ng + j;
            g_logits[gm * VV + gn] = acc[i][j] + vocb[gn];
        }
    }
}

// ---------------- cross entropy (deterministic 2-stage reduce) ----------------
__global__ void ce_rows_kernel(const int* __restrict__ Etok) {
    int gw = (blockIdx.x * blockDim.x + threadIdx.x) >> 5;
    int lane = threadIdx.x & 31;
    int nw = (gridDim.x * blockDim.x) >> 5;
    float nll = 0.f, cnt = 0.f;
    for (int r = gw; r < TDEC * BB; r += nw) {
        int tt = r >> 7, b = r & 127;
        int tgt = Etok[b * LE + tt + 1];
        if (tgt == 0) continue;
        const float* row = g_logits + (size_t)r * VV;
        float v0 = row[lane], v1 = row[lane + 32], v2 = row[lane + 64], v3 = row[lane + 96];
        float mx = fmaxf(fmaxf(v0, v1), fmaxf(v2, v3));
#pragma unroll
        for (int o = 16; o; o >>= 1) mx = fmaxf(mx, __shfl_xor_sync(0xffffffffu, mx, o));
        float se = __expf(v0 - mx) + __expf(v1 - mx) + __expf(v2 - mx) + __expf(v3 - mx);
#pragma unroll
        for (int o = 16; o; o >>= 1) se += __shfl_xor_sync(0xffffffffu, se, o);
        if (lane == 0) { nll += logf(se) + mx - row[tgt]; cnt += 1.f; }
    }
    __shared__ float sn[8], scn[8];
    int w = threadIdx.x >> 5;
    if (lane == 0) { sn[w] = nll; scn[w] = cnt; }
    __syncthreads();
    if (threadIdx.x == 0) {
        float a = 0.f, c2 = 0.f;
        for (int i = 0; i < 8; i++) { a += sn[i]; c2 += scn[i]; }
        g_part[blockIdx.x * 2] = a;
        g_part[blockIdx.x * 2 + 1] = c2;
    }
}

__global__ void ce_final_kernel(float* __restrict__ out) {
    if (threadIdx.x == 0) {
        float n = 0.f, c2 = 0.f;
        for (int i = 0; i < 256; i++) { n += g_part[2 * i]; c2 += g_part[2 * i + 1]; }
        out[0] = n / fmaxf(c2, 1.f);
    }
}

// ---------------- host orchestration (R4-proven launch order) ----------------
extern "C" void kernel_launch(void* const* d_in, const int* in_sizes, int n_in,
                              void* d_out, int out_size) {
    const float* C      = (const float*)d_in[0];
    const int*   C_pad  = (const int*)  d_in[1];
    const int*   E      = (const int*)  d_in[2];
    const float* E_emb  = (const float*)d_in[3];
    const float* eWih   = (const float*)d_in[4];
    const float* eWhh   = (const float*)d_in[5];
    const float* eBih   = (const float*)d_in[6];
    const float* eBhh   = (const float*)d_in[7];
    const float* dWih   = (const float*)d_in[8];
    const float* dWhh   = (const float*)d_in[9];
    const float* dBih   = (const float*)d_in[10];
    const float* dBhh   = (const float*)d_in[11];
    const float* attW   = (const float*)d_in[12];
    const float* outW   = (const float*)d_in[13];
    const float* outb   = (const float*)d_in[14];
    const float* vocW   = (const float*)d_in[15];
    const float* vocb   = (const float*)d_in[16];

    // Idempotent, called every invocation (no static guards per harness rules)
    cudaFuncSetAttribute(encoder_kernel,
        cudaFuncAttributeMaxDynamicSharedMemorySize, (int)sizeof(EncSmem));
    cudaFuncSetAttribute(decoder_kernel,
        cudaFuncAttributeMaxDynamicSharedMemorySize, (int)sizeof(DecSmem));

    prep_kernel<<<512, 256>>>(eWih, eWhh, eBih, eBhh, dWih, dWhh, dBih, dBhh);
    encoder_kernel<<<NCTA, 256, sizeof(EncSmem)>>>(C);
    decoder_kernel<<<NCTA, 256, sizeof(DecSmem)>>>(E_emb, C_pad, attW, outW, outb);
    vocab_kernel<<<dim3(VV / 32, (TDEC * BB) / 128), 256>>>(vocW, vocb);
    ce_rows_kernel<<<256, 256>>>(E);
    ce_final_kernel<<<1, 32>>>((float*)d_out);
}